// round 13
// baseline (speedup 1.0000x reference)
#include <cuda_runtime.h>
#include <math.h>
#include <stdint.h>

// Problem constants
#define BATCH  4
#define SEQ    2048
#define C_DIM  1024
#define H_DIM  16
#define D_DIM  64
#define M_DIM  (BATCH * SEQ)          // 8192
// softmax scale folded into q weights: D^-0.5 * log2(e)
#define QSCALE (0.125f * 1.4426950408889634f)

// ---------------------------------------------------------------------------
// Device scratch
// ---------------------------------------------------------------------------
__device__ float g_vw [C_DIM * C_DIM];
__device__ float g_pw [C_DIM * C_DIM];
__device__ float g_pb [C_DIM];
__device__ float g_xr [M_DIM * C_DIM];
__device__ float g_qwr[C_DIM * C_DIM];
__device__ float g_kwr[C_DIM * C_DIM];
__device__ float g_q  [M_DIM * C_DIM];
__device__ float g_k  [M_DIM * C_DIM];
__device__ float g_v  [M_DIM * C_DIM];
__device__ float g_o  [M_DIM * C_DIM];

// ---------------------------------------------------------------------------
// Helpers
// ---------------------------------------------------------------------------
__device__ __forceinline__ float f2tf(float x) {
    uint32_t u;
    asm("cvt.rna.tf32.f32 %0, %1;" : "=r"(u) : "f"(x));
    return __uint_as_float(u);
}
__device__ __forceinline__ float4 f2tf4(float4 v) {
    v.x = f2tf(v.x); v.y = f2tf(v.y); v.z = f2tf(v.z); v.w = f2tf(v.w);
    return v;
}
__device__ __forceinline__ float ex2f(float x) {
    float y;
    asm("ex2.approx.f32 %0, %1;" : "=f"(y) : "f"(x));
    return y;
}
__device__ __forceinline__ void mma_tf32(float* d,
                                         uint32_t a0, uint32_t a1, uint32_t a2, uint32_t a3,
                                         uint32_t b0, uint32_t b1)
{
    asm volatile(
        "mma.sync.aligned.m16n8k8.row.col.f32.tf32.tf32.f32 "
        "{%0,%1,%2,%3}, {%4,%5,%6,%7}, {%8,%9}, {%0,%1,%2,%3};\n"
        : "+f"(d[0]), "+f"(d[1]), "+f"(d[2]), "+f"(d[3])
        : "r"(a0), "r"(a1), "r"(a2), "r"(a3), "r"(b0), "r"(b1));
}
__device__ __forceinline__ void ldsm_x4(uint32_t& r0, uint32_t& r1,
                                        uint32_t& r2, uint32_t& r3, uint32_t addr)
{
    asm volatile("ldmatrix.sync.aligned.m8n8.x4.shared.b16 {%0,%1,%2,%3}, [%4];"
                 : "=r"(r0), "=r"(r1), "=r"(r2), "=r"(r3) : "r"(addr));
}
__device__ __forceinline__ uint32_t smem_u32(const void* p) {
    return (uint32_t)__cvta_generic_to_shared(p);
}
__device__ __forceinline__ void cp_async16(void* smem, const void* gmem) {
    uint32_t s = smem_u32(smem);
    asm volatile("cp.async.cg.shared.global [%0], [%1], 16;\n" :: "r"(s), "l"(gmem));
}
__device__ __forceinline__ void cp_commit() {
    asm volatile("cp.async.commit_group;\n");
}
template<int N> __device__ __forceinline__ void cp_wait() {
    asm volatile("cp.async.wait_group %0;\n" :: "n"(N));
}
__device__ __forceinline__ float bayes_w(float mu, float rho, float eps) {
    float sp = (rho > 15.0f) ? rho : log1pf(__expf(rho));
    return fmaf(sp, eps, mu);
}

// ---------------------------------------------------------------------------
// Prep kernels
// ---------------------------------------------------------------------------
__global__ void round_x_kernel(const float* __restrict__ in,
                               float* __restrict__ out, int n4)
{
    int i = blockIdx.x * 256 + threadIdx.x;
    if (i < n4) ((float4*)out)[i] = f2tf4(((const float4*)in)[i]);
}

__global__ void prep_w_kernel(const float* __restrict__ qw,  const float* __restrict__ kw,
                              const float* __restrict__ vmu, const float* __restrict__ vrho,
                              const float* __restrict__ veps,
                              const float* __restrict__ pmu, const float* __restrict__ prho,
                              const float* __restrict__ peps,
                              const float* __restrict__ pbmu, const float* __restrict__ pbrho,
                              const float* __restrict__ pbeps,
                              float* __restrict__ qwr, float* __restrict__ kwr,
                              float* __restrict__ vw,  float* __restrict__ pw,
                              float* __restrict__ pb)
{
    const int nw = C_DIM * C_DIM;
    int i = blockIdx.x * 256 + threadIdx.x;
    if (i < nw) {
        qwr[i] = f2tf(qw[i] * QSCALE);          // softmax scale folded here
    } else if (i < 2 * nw) {
        int j = i - nw;      kwr[j] = f2tf(kw[j]);
    } else if (i < 3 * nw) {
        int j = i - 2 * nw;  vw[j] = f2tf(bayes_w(vmu[j], vrho[j], veps[j]));
    } else if (i < 4 * nw) {
        int j = i - 3 * nw;  pw[j] = f2tf(bayes_w(pmu[j], prho[j], peps[j]));
    } else if (i < 4 * nw + C_DIM) {
        int j = i - 4 * nw;  pb[j] = bayes_w(pbmu[j], pbrho[j], pbeps[j]);
    }
}

// ---------------------------------------------------------------------------
// TF32 SGEMM (NT): 3-stage cp.async pipeline (ONE barrier per chunk) +
// ldmatrix fragment loads. 128x128x32 tile, 256 threads = 8 warps (2Mx4N),
// warp tile 64x32. Refill targets the stage computed 2 iters ago, so the
// iteration-entry barrier alone guarantees reuse safety.
// ---------------------------------------------------------------------------
#define GBM 128
#define GBN 128
#define GBK 32
#define GSTR 36
#define GTILE (GBM * GSTR)
#define GSTG 3
#define GEMM_SMEM (2 * GSTG * GTILE * 4)   // 110592 B

__global__ __launch_bounds__(256, 2)
void sgemm_tf32(const float* __restrict__ A, const float* __restrict__ B,
                const float* __restrict__ bias, float* __restrict__ Cmat,
                int Kdim, int Ndim, int round_out)
{
    extern __shared__ float sm[];
    float* As = sm;                    // [3][GTILE]
    float* Bs = sm + GSTG * GTILE;     // [3][GTILE]

    const int tid  = threadIdx.x;
    const int lane = tid & 31;
    const int w    = tid >> 5;
    const int wm   = w >> 2;
    const int wn   = w & 3;
    const int g    = lane >> 2;
    const int t    = lane & 3;
    const int m0   = blockIdx.y * GBM;
    const int n0   = blockIdx.x * GBN;

    // ldmatrix per-lane byte offsets (A pattern / B pattern)
    const uint32_t offA = ((lane & 15) * GSTR) * 4 + (lane >> 4) * 16;
    const uint32_t offB = (((lane & 7) + ((lane & 16) >> 1)) * GSTR) * 4 +
                          ((lane >> 3) & 1) * 16;
    const uint32_t uAs = smem_u32(As);
    const uint32_t uBs = smem_u32(Bs);

    float acc[4][4][4];
#pragma unroll
    for (int i = 0; i < 4; i++)
#pragma unroll
        for (int j = 0; j < 4; j++)
#pragma unroll
            for (int c = 0; c < 4; c++) acc[i][j][c] = 0.0f;

    const int lrow = tid >> 3;              // 0..31
    const int lsg  = (tid & 7) * 4;         // 0,4,...,28
    const int NCH  = Kdim / GBK;            // 32

    #define LOAD_TILES(st, c)                                                   \
        do {                                                                    \
            int k0 = (c) * GBK;                                                 \
            _Pragma("unroll")                                                   \
            for (int it = 0; it < 4; it++) {                                    \
                int row = lrow + it * 32;                                       \
                cp_async16(&As[(st) * GTILE + row * GSTR + lsg],                \
                           A + (size_t)(m0 + row) * Kdim + k0 + lsg);           \
                cp_async16(&Bs[(st) * GTILE + row * GSTR + lsg],                \
                           B + (size_t)(n0 + row) * Kdim + k0 + lsg);           \
            }                                                                   \
            cp_commit();                                                        \
        } while (0)

    LOAD_TILES(0, 0);
    LOAD_TILES(1, 1);

    for (int c = 0; c < NCH; c++) {
        if (c + 2 < NCH) cp_wait<1>();
        else             cp_wait<0>();
        __syncthreads();
        if (c + 2 < NCH) LOAD_TILES((c + 2) % GSTG, c + 2);

        const int s = c % GSTG;
        const uint32_t aBase = uAs + s * GTILE * 4;
        const uint32_t bBase = uBs + s * GTILE * 4;
#pragma unroll
        for (int kk = 0; kk < 4; kk++) {
            const uint32_t kbB = kk * 32;   // kk*8 floats
            uint32_t af[4][4];
#pragma unroll
            for (int mt = 0; mt < 4; mt++)
                ldsm_x4(af[mt][0], af[mt][1], af[mt][2], af[mt][3],
                        aBase + (uint32_t)(wm * 64 + mt * 16) * GSTR * 4 + offA + kbB);
            uint32_t bf[4][2];
#pragma unroll
            for (int p = 0; p < 2; p++)
                ldsm_x4(bf[2 * p][0], bf[2 * p][1], bf[2 * p + 1][0], bf[2 * p + 1][1],
                        bBase + (uint32_t)(wn * 32 + p * 16) * GSTR * 4 + offB + kbB);
#pragma unroll
            for (int mt = 0; mt < 4; mt++)
#pragma unroll
                for (int nt = 0; nt < 4; nt++)
                    mma_tf32(acc[mt][nt], af[mt][0], af[mt][1], af[mt][2], af[mt][3],
                             bf[nt][0], bf[nt][1]);
        }
    }
    #undef LOAD_TILES

    // Epilogue
#pragma unroll
    for (int mt = 0; mt < 4; mt++) {
        int r0 = m0 + wm * 64 + mt * 16 + g;
#pragma unroll
        for (int nt = 0; nt < 4; nt++) {
            int c0 = n0 + wn * 32 + nt * 8 + 2 * t;
            float bx = 0.0f, by = 0.0f;
            if (bias) { bx = bias[c0]; by = bias[c0 + 1]; }
            float2 v0 = make_float2(acc[mt][nt][0] + bx, acc[mt][nt][1] + by);
            float2 v1 = make_float2(acc[mt][nt][2] + bx, acc[mt][nt][3] + by);
            if (round_out) {
                v0.x = f2tf(v0.x); v0.y = f2tf(v0.y);
                v1.x = f2tf(v1.x); v1.y = f2tf(v1.y);
            }
            *(float2*)(Cmat + (size_t)r0 * Ndim + c0)       = v0;
            *(float2*)(Cmat + (size_t)(r0 + 8) * Ndim + c0) = v1;
        }
    }
}

// ---------------------------------------------------------------------------
// TF32 flash attention, BQ=128 (identical to R8 passing version).
// 256 threads = 8 warps, warp owns 16 S-rows. BK = 64, D = 64.
// ---------------------------------------------------------------------------
#define FBQ   128
#define FSTR  68
#define VSTR  72
#define KTILE (64 * FSTR)
#define VTILE (64 * VSTR)
#define PTILE (FBQ * FSTR)
#define FLASH_SMEM ((2 * KTILE + 2 * VTILE + PTILE) * 4)   // 106496 B

__global__ __launch_bounds__(256, 2)
void flash_tf32(const float* __restrict__ Q, const float* __restrict__ K,
                const float* __restrict__ V, float* __restrict__ O)
{
    extern __shared__ float sm[];
    float* Ks = sm;
    float* Vs = sm + 2 * KTILE;
    float* Ps = sm + 2 * KTILE + 2 * VTILE;

    const int tid  = threadIdx.x;
    const int lane = tid & 31;
    const int w    = tid >> 5;
    const int g    = lane >> 2;
    const int t    = lane & 3;
    const int rb   = w * 16;
    const int bh   = blockIdx.y;
    const int b    = bh >> 4;
    const int h    = bh & 15;
    const int q0   = blockIdx.x * FBQ;

    const size_t baseQ  = ((size_t)b * SEQ + q0) * C_DIM + h * D_DIM;
    const size_t baseKV = ((size_t)b * SEQ) * C_DIM + h * D_DIM;

    const int lrow = tid >> 4;
    const int ldq  = (tid & 15) * 4;

    const uint32_t uKs = smem_u32(Ks);
    const uint32_t uPs = smem_u32(Ps);
    const uint32_t offA = ((lane & 15) * FSTR) * 4 + (lane >> 4) * 16;
    const uint32_t offB = (((lane & 7) + ((lane & 16) >> 1)) * FSTR) * 4 +
                          ((lane >> 3) & 1) * 16;

    #define LOAD_KV(st, kt)                                                     \
        do {                                                                    \
            _Pragma("unroll")                                                   \
            for (int it = 0; it < 4; it++) {                                    \
                int row = lrow + it * 16;                                       \
                cp_async16(&Ks[(st) * KTILE + row * FSTR + ldq],                \
                           K + baseKV + (size_t)((kt) + row) * C_DIM + ldq);    \
                cp_async16(&Vs[(st) * VTILE + row * VSTR + ldq],                \
                           V + baseKV + (size_t)((kt) + row) * C_DIM + ldq);    \
            }                                                                   \
            cp_commit();                                                        \
        } while (0)

    LOAD_KV(0, 0);

#pragma unroll
    for (int it = 0; it < 8; it++) {
        int row = lrow + it * 16;
        *(float4*)&Ps[row * FSTR + ldq] =
            *(const float4*)(Q + baseQ + (size_t)row * C_DIM + ldq);
    }
    __syncthreads();

    uint32_t qf[8][4];
#pragma unroll
    for (int kk = 0; kk < 8; kk++)
        ldsm_x4(qf[kk][0], qf[kk][1], qf[kk][2], qf[kk][3],
                uPs + (uint32_t)rb * FSTR * 4 + offA + kk * 32);

    float m0 = -1e30f, m1 = -1e30f, l0 = 0.0f, l1 = 0.0f;
    float oacc[8][4];
#pragma unroll
    for (int nt = 0; nt < 8; nt++)
#pragma unroll
        for (int c = 0; c < 4; c++) oacc[nt][c] = 0.0f;

    int st = 0;
    for (int kt = 0; kt < SEQ; kt += 64) {
        if (kt + 64 < SEQ) { LOAD_KV(st ^ 1, kt + 64); cp_wait<1>(); }
        else               { cp_wait<0>(); }
        __syncthreads();

        const uint32_t kBase = uKs + st * KTILE * 4;
        const float*   Vc    = Vs + st * VTILE;

        float s[8][4];
#pragma unroll
        for (int nt = 0; nt < 8; nt++)
#pragma unroll
            for (int c = 0; c < 4; c++) s[nt][c] = 0.0f;

#pragma unroll
        for (int kk = 0; kk < 8; kk++) {
            const uint32_t kbB = kk * 32;
#pragma unroll
            for (int p = 0; p < 4; p++) {
                uint32_t b0, b1, b2, b3;
                ldsm_x4(b0, b1, b2, b3,
                        kBase + (uint32_t)(p * 16) * FSTR * 4 + offB + kbB);
                mma_tf32(s[2 * p],     qf[kk][0], qf[kk][1], qf[kk][2], qf[kk][3], b0, b1);
                mma_tf32(s[2 * p + 1], qf[kk][0], qf[kk][1], qf[kk][2], qf[kk][3], b2, b3);
            }
        }

        float mx0 = -1e30f, mx1 = -1e30f;
#pragma unroll
        for (int nt = 0; nt < 8; nt++) {
            mx0 = fmaxf(mx0, fmaxf(s[nt][0], s[nt][1]));
            mx1 = fmaxf(mx1, fmaxf(s[nt][2], s[nt][3]));
        }
#pragma unroll
        for (int off = 1; off < 4; off <<= 1) {
            mx0 = fmaxf(mx0, __shfl_xor_sync(0xffffffffu, mx0, off));
            mx1 = fmaxf(mx1, __shfl_xor_sync(0xffffffffu, mx1, off));
        }
        float mn0 = fmaxf(m0, mx0), mn1 = fmaxf(m1, mx1);
        float cr0 = ex2f(m0 - mn0), cr1 = ex2f(m1 - mn1);
        float sum0 = 0.0f, sum1 = 0.0f;
#pragma unroll
        for (int nt = 0; nt < 8; nt++) {
            s[nt][0] = ex2f(s[nt][0] - mn0);
            s[nt][1] = ex2f(s[nt][1] - mn0);
            s[nt][2] = ex2f(s[nt][2] - mn1);
            s[nt][3] = ex2f(s[nt][3] - mn1);
            sum0 += s[nt][0] + s[nt][1];
            sum1 += s[nt][2] + s[nt][3];
        }
#pragma unroll
        for (int off = 1; off < 4; off <<= 1) {
            sum0 += __shfl_xor_sync(0xffffffffu, sum0, off);
            sum1 += __shfl_xor_sync(0xffffffffu, sum1, off);
        }
        l0 = l0 * cr0 + sum0;  m0 = mn0;
        l1 = l1 * cr1 + sum1;  m1 = mn1;
#pragma unroll
        for (int nt = 0; nt < 8; nt++) {
            oacc[nt][0] *= cr0; oacc[nt][1] *= cr0;
            oacc[nt][2] *= cr1; oacc[nt][3] *= cr1;
        }

#pragma unroll
        for (int nt = 0; nt < 8; nt++) {
            *(float2*)&Ps[(rb + g    ) * FSTR + nt * 8 + 2 * t] =
                make_float2(f2tf(s[nt][0]), f2tf(s[nt][1]));
            *(float2*)&Ps[(rb + g + 8) * FSTR + nt * 8 + 2 * t] =
                make_float2(f2tf(s[nt][2]), f2tf(s[nt][3]));
        }
        __syncwarp();

#pragma unroll
        for (int kk = 0; kk < 8; kk++) {
            const int kb = kk * 8;
            uint32_t a0, a1, a2, a3;
            ldsm_x4(a0, a1, a2, a3,
                    uPs + (uint32_t)rb * FSTR * 4 + offA + kk * 32);
#pragma unroll
            for (int nt = 0; nt < 8; nt++) {
                uint32_t b0 = __float_as_uint(Vc[(kb + t    ) * VSTR + nt * 8 + g]);
                uint32_t b1 = __float_as_uint(Vc[(kb + t + 4) * VSTR + nt * 8 + g]);
                mma_tf32(oacc[nt], a0, a1, a2, a3, b0, b1);
            }
        }
        __syncthreads();
        st ^= 1;
    }
    #undef LOAD_KV

    float inv0 = 1.0f / l0, inv1 = 1.0f / l1;
#pragma unroll
    for (int nt = 0; nt < 8; nt++) {
        int c0 = nt * 8 + 2 * t;
        float2 v0 = make_float2(f2tf(oacc[nt][0] * inv0), f2tf(oacc[nt][1] * inv0));
        float2 v1 = make_float2(f2tf(oacc[nt][2] * inv1), f2tf(oacc[nt][3] * inv1));
        *(float2*)(O + baseQ + (size_t)(rb + g    ) * C_DIM + c0) = v0;
        *(float2*)(O + baseQ + (size_t)(rb + g + 8) * C_DIM + c0) = v1;
    }
}

// ---------------------------------------------------------------------------
// Launch: round_x, prep_w, gemm q, gemm k, gemm v, flash, gemm p
// ---------------------------------------------------------------------------
extern "C" void kernel_launch(void* const* d_in, const int* in_sizes, int n_in,
                              void* d_out, int out_size)
{
    const float* x     = (const float*)d_in[0];
    const float* q_w   = (const float*)d_in[1];
    const float* k_w   = (const float*)d_in[2];
    const float* v_mu  = (const float*)d_in[3];
    const float* v_rho = (const float*)d_in[4];
    const float* v_eps = (const float*)d_in[5];
    const float* p_mu  = (const float*)d_in[6];
    const float* p_rho = (const float*)d_in[7];
    const float* p_eps = (const float*)d_in[8];
    const float* pb_mu = (const float*)d_in[9];
    const float* pb_rho= (const float*)d_in[10];
    const float* pb_eps= (const float*)d_in[11];
    float* out = (float*)d_out;

    float *vw, *pw, *pb, *xr, *qwr, *kwr, *q, *k, *v, *o;
    cudaGetSymbolAddress((void**)&vw,  g_vw);
    cudaGetSymbolAddress((void**)&pw,  g_pw);
    cudaGetSymbolAddress((void**)&pb,  g_pb);
    cudaGetSymbolAddress((void**)&xr,  g_xr);
    cudaGetSymbolAddress((void**)&qwr, g_qwr);
    cudaGetSymbolAddress((void**)&kwr, g_kwr);
    cudaGetSymbolAddress((void**)&q,   g_q);
    cudaGetSymbolAddress((void**)&k,   g_k);
    cudaGetSymbolAddress((void**)&v,   g_v);
    cudaGetSymbolAddress((void**)&o,   g_o);

    cudaFuncSetAttribute(sgemm_tf32,
                         cudaFuncAttributeMaxDynamicSharedMemorySize, GEMM_SMEM);
    cudaFuncSetAttribute(flash_tf32,
                         cudaFuncAttributeMaxDynamicSharedMemorySize, FLASH_SMEM);

    const int nw  = C_DIM * C_DIM;
    const int nx4 = M_DIM * C_DIM / 4;
    const int npw = 4 * nw + C_DIM;

    round_x_kernel<<<(nx4 + 255) / 256, 256>>>(x, xr, nx4);
    prep_w_kernel<<<(npw + 255) / 256, 256>>>(q_w, k_w, v_mu, v_rho, v_eps,
                                              p_mu, p_rho, p_eps,
                                              pb_mu, pb_rho, pb_eps,
                                              qwr, kwr, vw, pw, pb);

    dim3 ggrid(C_DIM / GBN, M_DIM / GBM);
    sgemm_tf32<<<ggrid, 256, GEMM_SMEM>>>(xr, qwr, nullptr, q, C_DIM, C_DIM, 1);
    sgemm_tf32<<<ggrid, 256, GEMM_SMEM>>>(xr, kwr, nullptr, k, C_DIM, C_DIM, 1);
    sgemm_tf32<<<ggrid, 256, GEMM_SMEM>>>(xr, vw,  nullptr, v, C_DIM, C_DIM, 1);

    flash_tf32<<<dim3(SEQ / FBQ, BATCH * H_DIM), 256, FLASH_SMEM>>>(q, k, v, o);

    sgemm_tf32<<<ggrid, 256, GEMM_SMEM>>>(o, pw, pb, out, C_DIM, C_DIM, 0);
}

// round 14
// speedup vs baseline: 1.0464x; 1.0464x over previous
#include <cuda_runtime.h>
#include <math.h>
#include <stdint.h>

// Problem constants
#define BATCH  4
#define SEQ    2048
#define C_DIM  1024
#define H_DIM  16
#define D_DIM  64
#define M_DIM  (BATCH * SEQ)          // 8192
// softmax scale folded into q weights: D^-0.5 * log2(e)
#define QSCALE (0.125f * 1.4426950408889634f)

// ---------------------------------------------------------------------------
// Device scratch
// ---------------------------------------------------------------------------
__device__ float g_vw [C_DIM * C_DIM];
__device__ float g_pw [C_DIM * C_DIM];
__device__ float g_pb [C_DIM];
__device__ float g_xr [M_DIM * C_DIM];
__device__ float g_qwr[C_DIM * C_DIM];
__device__ float g_kwr[C_DIM * C_DIM];
__device__ float g_q  [M_DIM * C_DIM];
__device__ float g_k  [M_DIM * C_DIM];
__device__ float g_v  [M_DIM * C_DIM];
__device__ float g_o  [M_DIM * C_DIM];

// ---------------------------------------------------------------------------
// Helpers
// ---------------------------------------------------------------------------
__device__ __forceinline__ float f2tf(float x) {
    uint32_t u;
    asm("cvt.rna.tf32.f32 %0, %1;" : "=r"(u) : "f"(x));
    return __uint_as_float(u);
}
__device__ __forceinline__ float4 f2tf4(float4 v) {
    v.x = f2tf(v.x); v.y = f2tf(v.y); v.z = f2tf(v.z); v.w = f2tf(v.w);
    return v;
}
__device__ __forceinline__ float ex2f(float x) {
    float y;
    asm("ex2.approx.f32 %0, %1;" : "=f"(y) : "f"(x));
    return y;
}
__device__ __forceinline__ void mma_tf32(float* d,
                                         uint32_t a0, uint32_t a1, uint32_t a2, uint32_t a3,
                                         uint32_t b0, uint32_t b1)
{
    asm volatile(
        "mma.sync.aligned.m16n8k8.row.col.f32.tf32.tf32.f32 "
        "{%0,%1,%2,%3}, {%4,%5,%6,%7}, {%8,%9}, {%0,%1,%2,%3};\n"
        : "+f"(d[0]), "+f"(d[1]), "+f"(d[2]), "+f"(d[3])
        : "r"(a0), "r"(a1), "r"(a2), "r"(a3), "r"(b0), "r"(b1));
}
__device__ __forceinline__ void ldsm_x4(uint32_t& r0, uint32_t& r1,
                                        uint32_t& r2, uint32_t& r3, uint32_t addr)
{
    asm volatile("ldmatrix.sync.aligned.m8n8.x4.shared.b16 {%0,%1,%2,%3}, [%4];"
                 : "=r"(r0), "=r"(r1), "=r"(r2), "=r"(r3) : "r"(addr));
}
__device__ __forceinline__ uint32_t smem_u32(const void* p) {
    return (uint32_t)__cvta_generic_to_shared(p);
}
__device__ __forceinline__ void cp_async16(void* smem, const void* gmem) {
    uint32_t s = smem_u32(smem);
    asm volatile("cp.async.cg.shared.global [%0], [%1], 16;\n" :: "r"(s), "l"(gmem));
}
__device__ __forceinline__ void cp_commit() {
    asm volatile("cp.async.commit_group;\n");
}
template<int N> __device__ __forceinline__ void cp_wait() {
    asm volatile("cp.async.wait_group %0;\n" :: "n"(N));
}
__device__ __forceinline__ float bayes_w(float mu, float rho, float eps) {
    float sp = (rho > 15.0f) ? rho : log1pf(__expf(rho));
    return fmaf(sp, eps, mu);
}

// ---------------------------------------------------------------------------
// Prep kernels
// ---------------------------------------------------------------------------
__global__ void round_x_kernel(const float* __restrict__ in,
                               float* __restrict__ out, int n4)
{
    int i = blockIdx.x * 256 + threadIdx.x;
    if (i < n4) ((float4*)out)[i] = f2tf4(((const float4*)in)[i]);
}

__global__ void prep_w_kernel(const float* __restrict__ qw,  const float* __restrict__ kw,
                              const float* __restrict__ vmu, const float* __restrict__ vrho,
                              const float* __restrict__ veps,
                              const float* __restrict__ pmu, const float* __restrict__ prho,
                              const float* __restrict__ peps,
                              const float* __restrict__ pbmu, const float* __restrict__ pbrho,
                              const float* __restrict__ pbeps,
                              float* __restrict__ qwr, float* __restrict__ kwr,
                              float* __restrict__ vw,  float* __restrict__ pw,
                              float* __restrict__ pb)
{
    const int nw = C_DIM * C_DIM;
    int i = blockIdx.x * 256 + threadIdx.x;
    if (i < nw) {
        qwr[i] = f2tf(qw[i] * QSCALE);          // softmax scale folded here
    } else if (i < 2 * nw) {
        int j = i - nw;      kwr[j] = f2tf(kw[j]);
    } else if (i < 3 * nw) {
        int j = i - 2 * nw;  vw[j] = f2tf(bayes_w(vmu[j], vrho[j], veps[j]));
    } else if (i < 4 * nw) {
        int j = i - 3 * nw;  pw[j] = f2tf(bayes_w(pmu[j], prho[j], peps[j]));
    } else if (i < 4 * nw + C_DIM) {
        int j = i - 4 * nw;  pb[j] = bayes_w(pbmu[j], pbrho[j], pbeps[j]);
    }
}

// ---------------------------------------------------------------------------
// TF32 SGEMM (NT): 3-stage cp.async pipeline + ldmatrix fragment loads.
// 128x128x32 tile, 256 threads = 8 warps (2Mx4N), warp tile 64x32.
// (identical to R13 passing version)
// ---------------------------------------------------------------------------
#define GBM 128
#define GBN 128
#define GBK 32
#define GSTR 36
#define GTILE (GBM * GSTR)
#define GSTG 3
#define GEMM_SMEM (2 * GSTG * GTILE * 4)   // 110592 B

__global__ __launch_bounds__(256, 2)
void sgemm_tf32(const float* __restrict__ A, const float* __restrict__ B,
                const float* __restrict__ bias, float* __restrict__ Cmat,
                int Kdim, int Ndim, int round_out)
{
    extern __shared__ float sm[];
    float* As = sm;                    // [3][GTILE]
    float* Bs = sm + GSTG * GTILE;     // [3][GTILE]

    const int tid  = threadIdx.x;
    const int lane = tid & 31;
    const int w    = tid >> 5;
    const int wm   = w >> 2;
    const int wn   = w & 3;
    const int g    = lane >> 2;
    const int t    = lane & 3;
    const int m0   = blockIdx.y * GBM;
    const int n0   = blockIdx.x * GBN;

    const uint32_t offA = ((lane & 15) * GSTR) * 4 + (lane >> 4) * 16;
    const uint32_t offB = (((lane & 7) + ((lane & 16) >> 1)) * GSTR) * 4 +
                          ((lane >> 3) & 1) * 16;
    const uint32_t uAs = smem_u32(As);
    const uint32_t uBs = smem_u32(Bs);

    float acc[4][4][4];
#pragma unroll
    for (int i = 0; i < 4; i++)
#pragma unroll
        for (int j = 0; j < 4; j++)
#pragma unroll
            for (int c = 0; c < 4; c++) acc[i][j][c] = 0.0f;

    const int lrow = tid >> 3;              // 0..31
    const int lsg  = (tid & 7) * 4;         // 0,4,...,28
    const int NCH  = Kdim / GBK;            // 32

    #define LOAD_TILES(st, c)                                                   \
        do {                                                                    \
            int k0 = (c) * GBK;                                                 \
            _Pragma("unroll")                                                   \
            for (int it = 0; it < 4; it++) {                                    \
                int row = lrow + it * 32;                                       \
                cp_async16(&As[(st) * GTILE + row * GSTR + lsg],                \
                           A + (size_t)(m0 + row) * Kdim + k0 + lsg);           \
                cp_async16(&Bs[(st) * GTILE + row * GSTR + lsg],                \
                           B + (size_t)(n0 + row) * Kdim + k0 + lsg);           \
            }                                                                   \
            cp_commit();                                                        \
        } while (0)

    LOAD_TILES(0, 0);
    LOAD_TILES(1, 1);

    for (int c = 0; c < NCH; c++) {
        if (c + 2 < NCH) cp_wait<1>();
        else             cp_wait<0>();
        __syncthreads();
        if (c + 2 < NCH) LOAD_TILES((c + 2) % GSTG, c + 2);

        const int s = c % GSTG;
        const uint32_t aBase = uAs + s * GTILE * 4;
        const uint32_t bBase = uBs + s * GTILE * 4;
#pragma unroll
        for (int kk = 0; kk < 4; kk++) {
            const uint32_t kbB = kk * 32;   // kk*8 floats
            uint32_t af[4][4];
#pragma unroll
            for (int mt = 0; mt < 4; mt++)
                ldsm_x4(af[mt][0], af[mt][1], af[mt][2], af[mt][3],
                        aBase + (uint32_t)(wm * 64 + mt * 16) * GSTR * 4 + offA + kbB);
            uint32_t bf[4][2];
#pragma unroll
            for (int p = 0; p < 2; p++)
                ldsm_x4(bf[2 * p][0], bf[2 * p][1], bf[2 * p + 1][0], bf[2 * p + 1][1],
                        bBase + (uint32_t)(wn * 32 + p * 16) * GSTR * 4 + offB + kbB);
#pragma unroll
            for (int mt = 0; mt < 4; mt++)
#pragma unroll
                for (int nt = 0; nt < 4; nt++)
                    mma_tf32(acc[mt][nt], af[mt][0], af[mt][1], af[mt][2], af[mt][3],
                             bf[nt][0], bf[nt][1]);
        }
    }
    #undef LOAD_TILES

    // Epilogue
#pragma unroll
    for (int mt = 0; mt < 4; mt++) {
        int r0 = m0 + wm * 64 + mt * 16 + g;
#pragma unroll
        for (int nt = 0; nt < 4; nt++) {
            int c0 = n0 + wn * 32 + nt * 8 + 2 * t;
            float bx = 0.0f, by = 0.0f;
            if (bias) { bx = bias[c0]; by = bias[c0 + 1]; }
            float2 v0 = make_float2(acc[mt][nt][0] + bx, acc[mt][nt][1] + by);
            float2 v1 = make_float2(acc[mt][nt][2] + bx, acc[mt][nt][3] + by);
            if (round_out) {
                v0.x = f2tf(v0.x); v0.y = f2tf(v0.y);
                v1.x = f2tf(v1.x); v1.y = f2tf(v1.y);
            }
            *(float2*)(Cmat + (size_t)r0 * Ndim + c0)       = v0;
            *(float2*)(Cmat + (size_t)(r0 + 8) * Ndim + c0) = v1;
        }
    }
}

// ---------------------------------------------------------------------------
// TF32 flash attention, BQ=128 (identical to R8/R13 passing version).
// ---------------------------------------------------------------------------
#define FBQ   128
#define FSTR  68
#define VSTR  72
#define KTILE (64 * FSTR)
#define VTILE (64 * VSTR)
#define PTILE (FBQ * FSTR)
#define FLASH_SMEM ((2 * KTILE + 2 * VTILE + PTILE) * 4)   // 106496 B

__global__ __launch_bounds__(256, 2)
void flash_tf32(const float* __restrict__ Q, const float* __restrict__ K,
                const float* __restrict__ V, float* __restrict__ O)
{
    extern __shared__ float sm[];
    float* Ks = sm;
    float* Vs = sm + 2 * KTILE;
    float* Ps = sm + 2 * KTILE + 2 * VTILE;

    const int tid  = threadIdx.x;
    const int lane = tid & 31;
    const int w    = tid >> 5;
    const int g    = lane >> 2;
    const int t    = lane & 3;
    const int rb   = w * 16;
    const int bh   = blockIdx.y;
    const int b    = bh >> 4;
    const int h    = bh & 15;
    const int q0   = blockIdx.x * FBQ;

    const size_t baseQ  = ((size_t)b * SEQ + q0) * C_DIM + h * D_DIM;
    const size_t baseKV = ((size_t)b * SEQ) * C_DIM + h * D_DIM;

    const int lrow = tid >> 4;
    const int ldq  = (tid & 15) * 4;

    const uint32_t uKs = smem_u32(Ks);
    const uint32_t uPs = smem_u32(Ps);
    const uint32_t offA = ((lane & 15) * FSTR) * 4 + (lane >> 4) * 16;
    const uint32_t offB = (((lane & 7) + ((lane & 16) >> 1)) * FSTR) * 4 +
                          ((lane >> 3) & 1) * 16;

    #define LOAD_KV(st, kt)                                                     \
        do {                                                                    \
            _Pragma("unroll")                                                   \
            for (int it = 0; it < 4; it++) {                                    \
                int row = lrow + it * 16;                                       \
                cp_async16(&Ks[(st) * KTILE + row * FSTR + ldq],                \
                           K + baseKV + (size_t)((kt) + row) * C_DIM + ldq);    \
                cp_async16(&Vs[(st) * VTILE + row * VSTR + ldq],                \
                           V + baseKV + (size_t)((kt) + row) * C_DIM + ldq);    \
            }                                                                   \
            cp_commit();                                                        \
        } while (0)

    LOAD_KV(0, 0);

#pragma unroll
    for (int it = 0; it < 8; it++) {
        int row = lrow + it * 16;
        *(float4*)&Ps[row * FSTR + ldq] =
            *(const float4*)(Q + baseQ + (size_t)row * C_DIM + ldq);
    }
    __syncthreads();

    uint32_t qf[8][4];
#pragma unroll
    for (int kk = 0; kk < 8; kk++)
        ldsm_x4(qf[kk][0], qf[kk][1], qf[kk][2], qf[kk][3],
                uPs + (uint32_t)rb * FSTR * 4 + offA + kk * 32);

    float m0 = -1e30f, m1 = -1e30f, l0 = 0.0f, l1 = 0.0f;
    float oacc[8][4];
#pragma unroll
    for (int nt = 0; nt < 8; nt++)
#pragma unroll
        for (int c = 0; c < 4; c++) oacc[nt][c] = 0.0f;

    int st = 0;
    for (int kt = 0; kt < SEQ; kt += 64) {
        if (kt + 64 < SEQ) { LOAD_KV(st ^ 1, kt + 64); cp_wait<1>(); }
        else               { cp_wait<0>(); }
        __syncthreads();

        const uint32_t kBase = uKs + st * KTILE * 4;
        const float*   Vc    = Vs + st * VTILE;

        float s[8][4];
#pragma unroll
        for (int nt = 0; nt < 8; nt++)
#pragma unroll
            for (int c = 0; c < 4; c++) s[nt][c] = 0.0f;

#pragma unroll
        for (int kk = 0; kk < 8; kk++) {
            const uint32_t kbB = kk * 32;
#pragma unroll
            for (int p = 0; p < 4; p++) {
                uint32_t b0, b1, b2, b3;
                ldsm_x4(b0, b1, b2, b3,
                        kBase + (uint32_t)(p * 16) * FSTR * 4 + offB + kbB);
                mma_tf32(s[2 * p],     qf[kk][0], qf[kk][1], qf[kk][2], qf[kk][3], b0, b1);
                mma_tf32(s[2 * p + 1], qf[kk][0], qf[kk][1], qf[kk][2], qf[kk][3], b2, b3);
            }
        }

        float mx0 = -1e30f, mx1 = -1e30f;
#pragma unroll
        for (int nt = 0; nt < 8; nt++) {
            mx0 = fmaxf(mx0, fmaxf(s[nt][0], s[nt][1]));
            mx1 = fmaxf(mx1, fmaxf(s[nt][2], s[nt][3]));
        }
#pragma unroll
        for (int off = 1; off < 4; off <<= 1) {
            mx0 = fmaxf(mx0, __shfl_xor_sync(0xffffffffu, mx0, off));
            mx1 = fmaxf(mx1, __shfl_xor_sync(0xffffffffu, mx1, off));
        }
        float mn0 = fmaxf(m0, mx0), mn1 = fmaxf(m1, mx1);
        float cr0 = ex2f(m0 - mn0), cr1 = ex2f(m1 - mn1);
        float sum0 = 0.0f, sum1 = 0.0f;
#pragma unroll
        for (int nt = 0; nt < 8; nt++) {
            s[nt][0] = ex2f(s[nt][0] - mn0);
            s[nt][1] = ex2f(s[nt][1] - mn0);
            s[nt][2] = ex2f(s[nt][2] - mn1);
            s[nt][3] = ex2f(s[nt][3] - mn1);
            sum0 += s[nt][0] + s[nt][1];
            sum1 += s[nt][2] + s[nt][3];
        }
#pragma unroll
        for (int off = 1; off < 4; off <<= 1) {
            sum0 += __shfl_xor_sync(0xffffffffu, sum0, off);
            sum1 += __shfl_xor_sync(0xffffffffu, sum1, off);
        }
        l0 = l0 * cr0 + sum0;  m0 = mn0;
        l1 = l1 * cr1 + sum1;  m1 = mn1;
#pragma unroll
        for (int nt = 0; nt < 8; nt++) {
            oacc[nt][0] *= cr0; oacc[nt][1] *= cr0;
            oacc[nt][2] *= cr1; oacc[nt][3] *= cr1;
        }

#pragma unroll
        for (int nt = 0; nt < 8; nt++) {
            *(float2*)&Ps[(rb + g    ) * FSTR + nt * 8 + 2 * t] =
                make_float2(f2tf(s[nt][0]), f2tf(s[nt][1]));
            *(float2*)&Ps[(rb + g + 8) * FSTR + nt * 8 + 2 * t] =
                make_float2(f2tf(s[nt][2]), f2tf(s[nt][3]));
        }
        __syncwarp();

#pragma unroll
        for (int kk = 0; kk < 8; kk++) {
            const int kb = kk * 8;
            uint32_t a0, a1, a2, a3;
            ldsm_x4(a0, a1, a2, a3,
                    uPs + (uint32_t)rb * FSTR * 4 + offA + kk * 32);
#pragma unroll
            for (int nt = 0; nt < 8; nt++) {
                uint32_t b0 = __float_as_uint(Vc[(kb + t    ) * VSTR + nt * 8 + g]);
                uint32_t b1 = __float_as_uint(Vc[(kb + t + 4) * VSTR + nt * 8 + g]);
                mma_tf32(oacc[nt], a0, a1, a2, a3, b0, b1);
            }
        }
        __syncthreads();
        st ^= 1;
    }
    #undef LOAD_KV

    float inv0 = 1.0f / l0, inv1 = 1.0f / l1;
#pragma unroll
    for (int nt = 0; nt < 8; nt++) {
        int c0 = nt * 8 + 2 * t;
        float2 v0 = make_float2(f2tf(oacc[nt][0] * inv0), f2tf(oacc[nt][1] * inv0));
        float2 v1 = make_float2(f2tf(oacc[nt][2] * inv1), f2tf(oacc[nt][3] * inv1));
        *(float2*)(O + baseQ + (size_t)(rb + g    ) * C_DIM + c0) = v0;
        *(float2*)(O + baseQ + (size_t)(rb + g + 8) * C_DIM + c0) = v1;
    }
}

// ---------------------------------------------------------------------------
// Launch: fork-join multi-stream capture.
//   default: round_x ─┬─> gemmQ ──┐
//   s1:      prep_w ──┼─> gemmK ──┼─> flash -> final gemm  (default stream)
//   s2:               └─> gemmV ──┘
// Streams/events created once on first (uncaptured) call; event record/wait
// inside capture become graph dependencies. No device allocation anywhere.
// ---------------------------------------------------------------------------
extern "C" void kernel_launch(void* const* d_in, const int* in_sizes, int n_in,
                              void* d_out, int out_size)
{
    const float* x     = (const float*)d_in[0];
    const float* q_w   = (const float*)d_in[1];
    const float* k_w   = (const float*)d_in[2];
    const float* v_mu  = (const float*)d_in[3];
    const float* v_rho = (const float*)d_in[4];
    const float* v_eps = (const float*)d_in[5];
    const float* p_mu  = (const float*)d_in[6];
    const float* p_rho = (const float*)d_in[7];
    const float* p_eps = (const float*)d_in[8];
    const float* pb_mu = (const float*)d_in[9];
    const float* pb_rho= (const float*)d_in[10];
    const float* pb_eps= (const float*)d_in[11];
    float* out = (float*)d_out;

    float *vw, *pw, *pb, *xr, *qwr, *kwr, *q, *k, *v, *o;
    cudaGetSymbolAddress((void**)&vw,  g_vw);
    cudaGetSymbolAddress((void**)&pw,  g_pw);
    cudaGetSymbolAddress((void**)&pb,  g_pb);
    cudaGetSymbolAddress((void**)&xr,  g_xr);
    cudaGetSymbolAddress((void**)&qwr, g_qwr);
    cudaGetSymbolAddress((void**)&kwr, g_kwr);
    cudaGetSymbolAddress((void**)&q,   g_q);
    cudaGetSymbolAddress((void**)&k,   g_k);
    cudaGetSymbolAddress((void**)&v,   g_v);
    cudaGetSymbolAddress((void**)&o,   g_o);

    static cudaStream_t s1 = nullptr, s2 = nullptr;
    static cudaEvent_t  e0 = nullptr, eX = nullptr, eW = nullptr,
                        eK = nullptr, eV = nullptr;
    if (!s1) {
        cudaStreamCreateWithFlags(&s1, cudaStreamNonBlocking);
        cudaStreamCreateWithFlags(&s2, cudaStreamNonBlocking);
        cudaEventCreateWithFlags(&e0, cudaEventDisableTiming);
        cudaEventCreateWithFlags(&eX, cudaEventDisableTiming);
        cudaEventCreateWithFlags(&eW, cudaEventDisableTiming);
        cudaEventCreateWithFlags(&eK, cudaEventDisableTiming);
        cudaEventCreateWithFlags(&eV, cudaEventDisableTiming);
        cudaFuncSetAttribute(sgemm_tf32,
                             cudaFuncAttributeMaxDynamicSharedMemorySize, GEMM_SMEM);
        cudaFuncSetAttribute(flash_tf32,
                             cudaFuncAttributeMaxDynamicSharedMemorySize, FLASH_SMEM);
    }

    const int nw  = C_DIM * C_DIM;
    const int nx4 = M_DIM * C_DIM / 4;
    const int npw = 4 * nw + C_DIM;
    dim3 ggrid(C_DIM / GBN, M_DIM / GBM);

    // Fork prep: round_x on default, prep_w on s1.
    cudaEventRecord(e0, 0);
    cudaStreamWaitEvent(s1, e0, 0);
    cudaStreamWaitEvent(s2, e0, 0);

    round_x_kernel<<<(nx4 + 255) / 256, 256>>>(x, xr, nx4);
    cudaEventRecord(eX, 0);                      // xr ready

    prep_w_kernel<<<(npw + 255) / 256, 256, 0, s1>>>(
        q_w, k_w, v_mu, v_rho, v_eps, p_mu, p_rho, p_eps,
        pb_mu, pb_rho, pb_eps, qwr, kwr, vw, pw, pb);
    cudaEventRecord(eW, s1);                     // weights ready

    // QKV GEMMs in parallel: Q on default (has xr; wait weights),
    // K on s1 (has weights; wait xr), V on s2 (wait both).
    cudaStreamWaitEvent(0, eW, 0);
    cudaStreamWaitEvent(s1, eX, 0);
    cudaStreamWaitEvent(s2, eX, 0);
    cudaStreamWaitEvent(s2, eW, 0);

    sgemm_tf32<<<ggrid, 256, GEMM_SMEM>>>(xr, qwr, nullptr, q, C_DIM, C_DIM, 1);
    sgemm_tf32<<<ggrid, 256, GEMM_SMEM, s1>>>(xr, kwr, nullptr, k, C_DIM, C_DIM, 1);
    sgemm_tf32<<<ggrid, 256, GEMM_SMEM, s2>>>(xr, vw,  nullptr, v, C_DIM, C_DIM, 1);
    cudaEventRecord(eK, s1);
    cudaEventRecord(eV, s2);

    // Join: flash needs q, k, v.
    cudaStreamWaitEvent(0, eK, 0);
    cudaStreamWaitEvent(0, eV, 0);

    flash_tf32<<<dim3(SEQ / FBQ, BATCH * H_DIM), 256, FLASH_SMEM>>>(q, k, v, o);

    sgemm_tf32<<<ggrid, 256, GEMM_SMEM>>>(o, pw, pb, out, C_DIM, C_DIM, 0);
}

// round 16
// speedup vs baseline: 1.1226x; 1.0728x over previous
#include <cuda_runtime.h>
#include <math.h>
#include <stdint.h>

// Problem constants
#define BATCH  4
#define SEQ    2048
#define C_DIM  1024
#define H_DIM  16
#define D_DIM  64
#define M_DIM  (BATCH * SEQ)          // 8192
// softmax scale folded into q weights: D^-0.5 * log2(e)
#define QSCALE (0.125f * 1.4426950408889634f)

// ---------------------------------------------------------------------------
// Device scratch
// ---------------------------------------------------------------------------
__device__ float g_vw [C_DIM * C_DIM];
__device__ float g_pw [C_DIM * C_DIM];
__device__ float g_pb [C_DIM];
__device__ float g_xr [M_DIM * C_DIM];
__device__ float g_qwr[C_DIM * C_DIM];
__device__ float g_kwr[C_DIM * C_DIM];
__device__ float g_q  [M_DIM * C_DIM];
__device__ float g_k  [M_DIM * C_DIM];
__device__ float g_v  [M_DIM * C_DIM];
__device__ float g_o  [M_DIM * C_DIM];

// ---------------------------------------------------------------------------
// Helpers
// ---------------------------------------------------------------------------
__device__ __forceinline__ float f2tf(float x) {
    uint32_t u;
    asm("cvt.rna.tf32.f32 %0, %1;" : "=r"(u) : "f"(x));
    return __uint_as_float(u);
}
__device__ __forceinline__ float4 f2tf4(float4 v) {
    v.x = f2tf(v.x); v.y = f2tf(v.y); v.z = f2tf(v.z); v.w = f2tf(v.w);
    return v;
}
__device__ __forceinline__ float ex2f(float x) {
    float y;
    asm("ex2.approx.f32 %0, %1;" : "=f"(y) : "f"(x));
    return y;
}
__device__ __forceinline__ void mma_tf32(float* d,
                                         uint32_t a0, uint32_t a1, uint32_t a2, uint32_t a3,
                                         uint32_t b0, uint32_t b1)
{
    asm volatile(
        "mma.sync.aligned.m16n8k8.row.col.f32.tf32.tf32.f32 "
        "{%0,%1,%2,%3}, {%4,%5,%6,%7}, {%8,%9}, {%0,%1,%2,%3};\n"
        : "+f"(d[0]), "+f"(d[1]), "+f"(d[2]), "+f"(d[3])
        : "r"(a0), "r"(a1), "r"(a2), "r"(a3), "r"(b0), "r"(b1));
}
__device__ __forceinline__ void ldsm_x4(uint32_t& r0, uint32_t& r1,
                                        uint32_t& r2, uint32_t& r3, uint32_t addr)
{
    asm volatile("ldmatrix.sync.aligned.m8n8.x4.shared.b16 {%0,%1,%2,%3}, [%4];"
                 : "=r"(r0), "=r"(r1), "=r"(r2), "=r"(r3) : "r"(addr));
}
__device__ __forceinline__ uint32_t smem_u32(const void* p) {
    return (uint32_t)__cvta_generic_to_shared(p);
}
__device__ __forceinline__ void cp_async16(void* smem, const void* gmem) {
    uint32_t s = smem_u32(smem);
    asm volatile("cp.async.cg.shared.global [%0], [%1], 16;\n" :: "r"(s), "l"(gmem));
}
__device__ __forceinline__ void cp_commit() {
    asm volatile("cp.async.commit_group;\n");
}
template<int N> __device__ __forceinline__ void cp_wait() {
    asm volatile("cp.async.wait_group %0;\n" :: "n"(N));
}
__device__ __forceinline__ float bayes_w(float mu, float rho, float eps) {
    float sp = (rho > 15.0f) ? rho : log1pf(__expf(rho));
    return fmaf(sp, eps, mu);
}

// ---------------------------------------------------------------------------
// Prep kernels
// ---------------------------------------------------------------------------
__global__ void round_x_kernel(const float* __restrict__ in,
                               float* __restrict__ out, int n4)
{
    int i = blockIdx.x * 256 + threadIdx.x;
    if (i < n4) ((float4*)out)[i] = f2tf4(((const float4*)in)[i]);
}

__global__ void prep_w_kernel(const float* __restrict__ qw,  const float* __restrict__ kw,
                              const float* __restrict__ vmu, const float* __restrict__ vrho,
                              const float* __restrict__ veps,
                              const float* __restrict__ pmu, const float* __restrict__ prho,
                              const float* __restrict__ peps,
                              const float* __restrict__ pbmu, const float* __restrict__ pbrho,
                              const float* __restrict__ pbeps,
                              float* __restrict__ qwr, float* __restrict__ kwr,
                              float* __restrict__ vw,  float* __restrict__ pw,
                              float* __restrict__ pb)
{
    const int nw = C_DIM * C_DIM;
    int i = blockIdx.x * 256 + threadIdx.x;
    if (i < nw) {
        qwr[i] = f2tf(qw[i] * QSCALE);          // softmax scale folded here
    } else if (i < 2 * nw) {
        int j = i - nw;      kwr[j] = f2tf(kw[j]);
    } else if (i < 3 * nw) {
        int j = i - 2 * nw;  vw[j] = f2tf(bayes_w(vmu[j], vrho[j], veps[j]));
    } else if (i < 4 * nw) {
        int j = i - 3 * nw;  pw[j] = f2tf(bayes_w(pmu[j], prho[j], peps[j]));
    } else if (i < 4 * nw + C_DIM) {
        int j = i - 4 * nw;  pb[j] = bayes_w(pbmu[j], pbrho[j], pbeps[j]);
    }
}

// ---------------------------------------------------------------------------
// TF32 SGEMM (NT): 3-stage cp.async pipeline + ldmatrix fragment loads.
// 128x128x32 tile, 256 threads = 8 warps (2Mx4N), warp tile 64x32.
// m_base: row offset of this chunk (batch chunking).
// ---------------------------------------------------------------------------
#define GBM 128
#define GBN 128
#define GBK 32
#define GSTR 36
#define GTILE (GBM * GSTR)
#define GSTG 3
#define GEMM_SMEM (2 * GSTG * GTILE * 4)   // 110592 B

__global__ __launch_bounds__(256, 2)
void sgemm_tf32(const float* __restrict__ A, const float* __restrict__ B,
                const float* __restrict__ bias, float* __restrict__ Cmat,
                int Kdim, int Ndim, int round_out, int m_base)
{
    extern __shared__ float sm[];
    float* As = sm;                    // [3][GTILE]
    float* Bs = sm + GSTG * GTILE;     // [3][GTILE]

    const int tid  = threadIdx.x;
    const int lane = tid & 31;
    const int w    = tid >> 5;
    const int wm   = w >> 2;
    const int wn   = w & 3;
    const int g    = lane >> 2;
    const int t    = lane & 3;
    const int m0   = m_base + blockIdx.y * GBM;
    const int n0   = blockIdx.x * GBN;

    const uint32_t offA = ((lane & 15) * GSTR) * 4 + (lane >> 4) * 16;
    const uint32_t offB = (((lane & 7) + ((lane & 16) >> 1)) * GSTR) * 4 +
                          ((lane >> 3) & 1) * 16;
    const uint32_t uAs = smem_u32(As);
    const uint32_t uBs = smem_u32(Bs);

    float acc[4][4][4];
#pragma unroll
    for (int i = 0; i < 4; i++)
#pragma unroll
        for (int j = 0; j < 4; j++)
#pragma unroll
            for (int c = 0; c < 4; c++) acc[i][j][c] = 0.0f;

    const int lrow = tid >> 3;              // 0..31
    const int lsg  = (tid & 7) * 4;         // 0,4,...,28
    const int NCH  = Kdim / GBK;            // 32

    #define LOAD_TILES(st, c)                                                   \
        do {                                                                    \
            int k0 = (c) * GBK;                                                 \
            _Pragma("unroll")                                                   \
            for (int it = 0; it < 4; it++) {                                    \
                int row = lrow + it * 32;                                       \
                cp_async16(&As[(st) * GTILE + row * GSTR + lsg],                \
                           A + (size_t)(m0 + row) * Kdim + k0 + lsg);           \
                cp_async16(&Bs[(st) * GTILE + row * GSTR + lsg],                \
                           B + (size_t)(n0 + row) * Kdim + k0 + lsg);           \
            }                                                                   \
            cp_commit();                                                        \
        } while (0)

    LOAD_TILES(0, 0);
    LOAD_TILES(1, 1);

    for (int c = 0; c < NCH; c++) {
        if (c + 2 < NCH) cp_wait<1>();
        else             cp_wait<0>();
        __syncthreads();
        if (c + 2 < NCH) LOAD_TILES((c + 2) % GSTG, c + 2);

        const int s = c % GSTG;
        const uint32_t aBase = uAs + s * GTILE * 4;
        const uint32_t bBase = uBs + s * GTILE * 4;
#pragma unroll
        for (int kk = 0; kk < 4; kk++) {
            const uint32_t kbB = kk * 32;   // kk*8 floats
            uint32_t af[4][4];
#pragma unroll
            for (int mt = 0; mt < 4; mt++)
                ldsm_x4(af[mt][0], af[mt][1], af[mt][2], af[mt][3],
                        aBase + (uint32_t)(wm * 64 + mt * 16) * GSTR * 4 + offA + kbB);
            uint32_t bf[4][2];
#pragma unroll
            for (int p = 0; p < 2; p++)
                ldsm_x4(bf[2 * p][0], bf[2 * p][1], bf[2 * p + 1][0], bf[2 * p + 1][1],
                        bBase + (uint32_t)(wn * 32 + p * 16) * GSTR * 4 + offB + kbB);
#pragma unroll
            for (int mt = 0; mt < 4; mt++)
#pragma unroll
                for (int nt = 0; nt < 4; nt++)
                    mma_tf32(acc[mt][nt], af[mt][0], af[mt][1], af[mt][2], af[mt][3],
                             bf[nt][0], bf[nt][1]);
        }
    }
    #undef LOAD_TILES

    // Epilogue
#pragma unroll
    for (int mt = 0; mt < 4; mt++) {
        int r0 = m0 + wm * 64 + mt * 16 + g;
#pragma unroll
        for (int nt = 0; nt < 4; nt++) {
            int c0 = n0 + wn * 32 + nt * 8 + 2 * t;
            float bx = 0.0f, by = 0.0f;
            if (bias) { bx = bias[c0]; by = bias[c0 + 1]; }
            float2 v0 = make_float2(acc[mt][nt][0] + bx, acc[mt][nt][1] + by);
            float2 v1 = make_float2(acc[mt][nt][2] + bx, acc[mt][nt][3] + by);
            if (round_out) {
                v0.x = f2tf(v0.x); v0.y = f2tf(v0.y);
                v1.x = f2tf(v1.x); v1.y = f2tf(v1.y);
            }
            *(float2*)(Cmat + (size_t)r0 * Ndim + c0)       = v0;
            *(float2*)(Cmat + (size_t)(r0 + 8) * Ndim + c0) = v1;
        }
    }
}

// ---------------------------------------------------------------------------
// TF32 flash attention, BQ=128 (kernel body identical to R13/R14 passing
// version; bh_base selects the batch chunk).
// ---------------------------------------------------------------------------
#define FBQ   128
#define FSTR  68
#define VSTR  72
#define KTILE (64 * FSTR)
#define VTILE (64 * VSTR)
#define PTILE (FBQ * FSTR)
#define FLASH_SMEM ((2 * KTILE + 2 * VTILE + PTILE) * 4)   // 106496 B

__global__ __launch_bounds__(256, 2)
void flash_tf32(const float* __restrict__ Q, const float* __restrict__ K,
                const float* __restrict__ V, float* __restrict__ O, int bh_base)
{
    extern __shared__ float sm[];
    float* Ks = sm;
    float* Vs = sm + 2 * KTILE;
    float* Ps = sm + 2 * KTILE + 2 * VTILE;

    const int tid  = threadIdx.x;
    const int lane = tid & 31;
    const int w    = tid >> 5;
    const int g    = lane >> 2;
    const int t    = lane & 3;
    const int rb   = w * 16;
    const int bh   = bh_base + blockIdx.y;
    const int b    = bh >> 4;
    const int h    = bh & 15;
    const int q0   = blockIdx.x * FBQ;

    const size_t baseQ  = ((size_t)b * SEQ + q0) * C_DIM + h * D_DIM;
    const size_t baseKV = ((size_t)b * SEQ) * C_DIM + h * D_DIM;

    const int lrow = tid >> 4;
    const int ldq  = (tid & 15) * 4;

    const uint32_t uKs = smem_u32(Ks);
    const uint32_t uPs = smem_u32(Ps);
    const uint32_t offA = ((lane & 15) * FSTR) * 4 + (lane >> 4) * 16;
    const uint32_t offB = (((lane & 7) + ((lane & 16) >> 1)) * FSTR) * 4 +
                          ((lane >> 3) & 1) * 16;

    #define LOAD_KV(st, kt)                                                     \
        do {                                                                    \
            _Pragma("unroll")                                                   \
            for (int it = 0; it < 4; it++) {                                    \
                int row = lrow + it * 16;                                       \
                cp_async16(&Ks[(st) * KTILE + row * FSTR + ldq],                \
                           K + baseKV + (size_t)((kt) + row) * C_DIM + ldq);    \
                cp_async16(&Vs[(st) * VTILE + row * VSTR + ldq],                \
                           V + baseKV + (size_t)((kt) + row) * C_DIM + ldq);    \
            }                                                                   \
            cp_commit();                                                        \
        } while (0)

    LOAD_KV(0, 0);

#pragma unroll
    for (int it = 0; it < 8; it++) {
        int row = lrow + it * 16;
        *(float4*)&Ps[row * FSTR + ldq] =
            *(const float4*)(Q + baseQ + (size_t)row * C_DIM + ldq);
    }
    __syncthreads();

    uint32_t qf[8][4];
#pragma unroll
    for (int kk = 0; kk < 8; kk++)
        ldsm_x4(qf[kk][0], qf[kk][1], qf[kk][2], qf[kk][3],
                uPs + (uint32_t)rb * FSTR * 4 + offA + kk * 32);

    float m0 = -1e30f, m1 = -1e30f, l0 = 0.0f, l1 = 0.0f;
    float oacc[8][4];
#pragma unroll
    for (int nt = 0; nt < 8; nt++)
#pragma unroll
        for (int c = 0; c < 4; c++) oacc[nt][c] = 0.0f;

    int st = 0;
    for (int kt = 0; kt < SEQ; kt += 64) {
        if (kt + 64 < SEQ) { LOAD_KV(st ^ 1, kt + 64); cp_wait<1>(); }
        else               { cp_wait<0>(); }
        __syncthreads();

        const uint32_t kBase = uKs + st * KTILE * 4;
        const float*   Vc    = Vs + st * VTILE;

        float s[8][4];
#pragma unroll
        for (int nt = 0; nt < 8; nt++)
#pragma unroll
            for (int c = 0; c < 4; c++) s[nt][c] = 0.0f;

#pragma unroll
        for (int kk = 0; kk < 8; kk++) {
            const uint32_t kbB = kk * 32;
#pragma unroll
            for (int p = 0; p < 4; p++) {
                uint32_t b0, b1, b2, b3;
                ldsm_x4(b0, b1, b2, b3,
                        kBase + (uint32_t)(p * 16) * FSTR * 4 + offB + kbB);
                mma_tf32(s[2 * p],     qf[kk][0], qf[kk][1], qf[kk][2], qf[kk][3], b0, b1);
                mma_tf32(s[2 * p + 1], qf[kk][0], qf[kk][1], qf[kk][2], qf[kk][3], b2, b3);
            }
        }

        float mx0 = -1e30f, mx1 = -1e30f;
#pragma unroll
        for (int nt = 0; nt < 8; nt++) {
            mx0 = fmaxf(mx0, fmaxf(s[nt][0], s[nt][1]));
            mx1 = fmaxf(mx1, fmaxf(s[nt][2], s[nt][3]));
        }
#pragma unroll
        for (int off = 1; off < 4; off <<= 1) {
            mx0 = fmaxf(mx0, __shfl_xor_sync(0xffffffffu, mx0, off));
            mx1 = fmaxf(mx1, __shfl_xor_sync(0xffffffffu, mx1, off));
        }
        float mn0 = fmaxf(m0, mx0), mn1 = fmaxf(m1, mx1);
        float cr0 = ex2f(m0 - mn0), cr1 = ex2f(m1 - mn1);
        float sum0 = 0.0f, sum1 = 0.0f;
#pragma unroll
        for (int nt = 0; nt < 8; nt++) {
            s[nt][0] = ex2f(s[nt][0] - mn0);
            s[nt][1] = ex2f(s[nt][1] - mn0);
            s[nt][2] = ex2f(s[nt][2] - mn1);
            s[nt][3] = ex2f(s[nt][3] - mn1);
            sum0 += s[nt][0] + s[nt][1];
            sum1 += s[nt][2] + s[nt][3];
        }
#pragma unroll
        for (int off = 1; off < 4; off <<= 1) {
            sum0 += __shfl_xor_sync(0xffffffffu, sum0, off);
            sum1 += __shfl_xor_sync(0xffffffffu, sum1, off);
        }
        l0 = l0 * cr0 + sum0;  m0 = mn0;
        l1 = l1 * cr1 + sum1;  m1 = mn1;
#pragma unroll
        for (int nt = 0; nt < 8; nt++) {
            oacc[nt][0] *= cr0; oacc[nt][1] *= cr0;
            oacc[nt][2] *= cr1; oacc[nt][3] *= cr1;
        }

#pragma unroll
        for (int nt = 0; nt < 8; nt++) {
            *(float2*)&Ps[(rb + g    ) * FSTR + nt * 8 + 2 * t] =
                make_float2(f2tf(s[nt][0]), f2tf(s[nt][1]));
            *(float2*)&Ps[(rb + g + 8) * FSTR + nt * 8 + 2 * t] =
                make_float2(f2tf(s[nt][2]), f2tf(s[nt][3]));
        }
        __syncwarp();

#pragma unroll
        for (int kk = 0; kk < 8; kk++) {
            const int kb = kk * 8;
            uint32_t a0, a1, a2, a3;
            ldsm_x4(a0, a1, a2, a3,
                    uPs + (uint32_t)rb * FSTR * 4 + offA + kk * 32);
#pragma unroll
            for (int nt = 0; nt < 8; nt++) {
                uint32_t b0 = __float_as_uint(Vc[(kb + t    ) * VSTR + nt * 8 + g]);
                uint32_t b1 = __float_as_uint(Vc[(kb + t + 4) * VSTR + nt * 8 + g]);
                mma_tf32(oacc[nt], a0, a1, a2, a3, b0, b1);
            }
        }
        __syncthreads();
        st ^= 1;
    }
    #undef LOAD_KV

    float inv0 = 1.0f / l0, inv1 = 1.0f / l1;
#pragma unroll
    for (int nt = 0; nt < 8; nt++) {
        int c0 = nt * 8 + 2 * t;
        float2 v0 = make_float2(f2tf(oacc[nt][0] * inv0), f2tf(oacc[nt][1] * inv0));
        float2 v1 = make_float2(f2tf(oacc[nt][2] * inv1), f2tf(oacc[nt][3] * inv1));
        *(float2*)(O + baseQ + (size_t)(rb + g    ) * C_DIM + c0) = v0;
        *(float2*)(O + baseQ + (size_t)(rb + g + 8) * C_DIM + c0) = v1;
    }
}

// ---------------------------------------------------------------------------
// Launch: TWO independent half-batch chains (one created stream only).
//   default: round_x ──> chain A: QKV_A, flash_A, proj_A   (batches 0-1)
//   s1:      prep_w ───> chain B: QKV_B, flash_B, proj_B   (batches 2-3)
//   cross events: eX (xr ready), eW (weights ready), eB (chain B done).
// ---------------------------------------------------------------------------
extern "C" void kernel_launch(void* const* d_in, const int* in_sizes, int n_in,
                              void* d_out, int out_size)
{
    const float* x     = (const float*)d_in[0];
    const float* q_w   = (const float*)d_in[1];
    const float* k_w   = (const float*)d_in[2];
    const float* v_mu  = (const float*)d_in[3];
    const float* v_rho = (const float*)d_in[4];
    const float* v_eps = (const float*)d_in[5];
    const float* p_mu  = (const float*)d_in[6];
    const float* p_rho = (const float*)d_in[7];
    const float* p_eps = (const float*)d_in[8];
    const float* pb_mu = (const float*)d_in[9];
    const float* pb_rho= (const float*)d_in[10];
    const float* pb_eps= (const float*)d_in[11];
    float* out = (float*)d_out;

    float *vw, *pw, *pb, *xr, *qwr, *kwr, *q, *k, *v, *o;
    cudaGetSymbolAddress((void**)&vw,  g_vw);
    cudaGetSymbolAddress((void**)&pw,  g_pw);
    cudaGetSymbolAddress((void**)&pb,  g_pb);
    cudaGetSymbolAddress((void**)&xr,  g_xr);
    cudaGetSymbolAddress((void**)&qwr, g_qwr);
    cudaGetSymbolAddress((void**)&kwr, g_kwr);
    cudaGetSymbolAddress((void**)&q,   g_q);
    cudaGetSymbolAddress((void**)&k,   g_k);
    cudaGetSymbolAddress((void**)&v,   g_v);
    cudaGetSymbolAddress((void**)&o,   g_o);

    static cudaStream_t s1 = nullptr;
    static cudaEvent_t  e0 = nullptr, eX = nullptr, eW = nullptr, eB = nullptr;
    if (!s1) {
        cudaStreamCreateWithFlags(&s1, cudaStreamNonBlocking);
        cudaEventCreateWithFlags(&e0, cudaEventDisableTiming);
        cudaEventCreateWithFlags(&eX, cudaEventDisableTiming);
        cudaEventCreateWithFlags(&eW, cudaEventDisableTiming);
        cudaEventCreateWithFlags(&eB, cudaEventDisableTiming);
        cudaFuncSetAttribute(sgemm_tf32,
                             cudaFuncAttributeMaxDynamicSharedMemorySize, GEMM_SMEM);
        cudaFuncSetAttribute(flash_tf32,
                             cudaFuncAttributeMaxDynamicSharedMemorySize, FLASH_SMEM);
    }

    const int nw  = C_DIM * C_DIM;
    const int nx4 = M_DIM * C_DIM / 4;
    const int npw = 4 * nw + C_DIM;
    const int HB  = 2 * SEQ;                     // rows per half (2 batches)
    dim3 hgrid(C_DIM / GBN, HB / GBM);           // half-batch GEMM: 8x32
    dim3 fgrid(SEQ / FBQ, 2 * H_DIM);            // half-batch flash: 16x32

    // Fork prep.
    cudaEventRecord(e0, 0);
    cudaStreamWaitEvent(s1, e0, 0);

    round_x_kernel<<<(nx4 + 255) / 256, 256>>>(x, xr, nx4);
    cudaEventRecord(eX, 0);

    prep_w_kernel<<<(npw + 255) / 256, 256, 0, s1>>>(
        q_w, k_w, v_mu, v_rho, v_eps, p_mu, p_rho, p_eps,
        pb_mu, pb_rho, pb_eps, qwr, kwr, vw, pw, pb);
    cudaEventRecord(eW, s1);

    // Chain A (batches 0-1) on default; chain B (batches 2-3) on s1.
    cudaStreamWaitEvent(0, eW, 0);
    cudaStreamWaitEvent(s1, eX, 0);

    sgemm_tf32<<<hgrid, 256, GEMM_SMEM>>>(xr, qwr, nullptr, q, C_DIM, C_DIM, 1, 0);
    sgemm_tf32<<<hgrid, 256, GEMM_SMEM>>>(xr, kwr, nullptr, k, C_DIM, C_DIM, 1, 0);
    sgemm_tf32<<<hgrid, 256, GEMM_SMEM>>>(xr, vw,  nullptr, v, C_DIM, C_DIM, 1, 0);
    flash_tf32<<<fgrid, 256, FLASH_SMEM>>>(q, k, v, o, 0);
    sgemm_tf32<<<hgrid, 256, GEMM_SMEM>>>(o, pw, pb, out, C_DIM, C_DIM, 0, 0);

    sgemm_tf32<<<hgrid, 256, GEMM_SMEM, s1>>>(xr, qwr, nullptr, q, C_DIM, C_DIM, 1, HB);
    sgemm_tf32<<<hgrid, 256, GEMM_SMEM, s1>>>(xr, kwr, nullptr, k, C_DIM, C_DIM, 1, HB);
    sgemm_tf32<<<hgrid, 256, GEMM_SMEM, s1>>>(xr, vw,  nullptr, v, C_DIM, C_DIM, 1, HB);
    flash_tf32<<<fgrid, 256, FLASH_SMEM, s1>>>(q, k, v, o, 2 * H_DIM);
    sgemm_tf32<<<hgrid, 256, GEMM_SMEM, s1>>>(o, pw, pb, out, C_DIM, C_DIM, 0, HB);
    cudaEventRecord(eB, s1);

    // Join.
    cudaStreamWaitEvent(0, eB, 0);
}

// round 17
// speedup vs baseline: 1.1287x; 1.0054x over previous
#include <cuda_runtime.h>
#include <math.h>
#include <stdint.h>

// Problem constants
#define BATCH  4
#define SEQ    2048
#define C_DIM  1024
#define H_DIM  16
#define D_DIM  64
#define M_DIM  (BATCH * SEQ)          // 8192
#define QKVN   (3 * C_DIM)            // 3072 fused output width
// softmax scale folded into q weights: D^-0.5 * log2(e)
#define QSCALE (0.125f * 1.4426950408889634f)

// ---------------------------------------------------------------------------
// Device scratch
// ---------------------------------------------------------------------------
__device__ float g_qkvw[QKVN * C_DIM];   // packed [qwr | kwr | vw] rows
__device__ float g_pw  [C_DIM * C_DIM];
__device__ float g_pb  [C_DIM];
__device__ float g_xr  [M_DIM * C_DIM];
__device__ float g_qkv [M_DIM * QKVN];   // fused q|k|v per row
__device__ float g_o   [M_DIM * C_DIM];

// ---------------------------------------------------------------------------
// Helpers
// ---------------------------------------------------------------------------
__device__ __forceinline__ float f2tf(float x) {
    uint32_t u;
    asm("cvt.rna.tf32.f32 %0, %1;" : "=r"(u) : "f"(x));
    return __uint_as_float(u);
}
__device__ __forceinline__ float4 f2tf4(float4 v) {
    v.x = f2tf(v.x); v.y = f2tf(v.y); v.z = f2tf(v.z); v.w = f2tf(v.w);
    return v;
}
__device__ __forceinline__ float ex2f(float x) {
    float y;
    asm("ex2.approx.f32 %0, %1;" : "=f"(y) : "f"(x));
    return y;
}
__device__ __forceinline__ void mma_tf32(float* d,
                                         uint32_t a0, uint32_t a1, uint32_t a2, uint32_t a3,
                                         uint32_t b0, uint32_t b1)
{
    asm volatile(
        "mma.sync.aligned.m16n8k8.row.col.f32.tf32.tf32.f32 "
        "{%0,%1,%2,%3}, {%4,%5,%6,%7}, {%8,%9}, {%0,%1,%2,%3};\n"
        : "+f"(d[0]), "+f"(d[1]), "+f"(d[2]), "+f"(d[3])
        : "r"(a0), "r"(a1), "r"(a2), "r"(a3), "r"(b0), "r"(b1));
}
__device__ __forceinline__ void ldsm_x4(uint32_t& r0, uint32_t& r1,
                                        uint32_t& r2, uint32_t& r3, uint32_t addr)
{
    asm volatile("ldmatrix.sync.aligned.m8n8.x4.shared.b16 {%0,%1,%2,%3}, [%4];"
                 : "=r"(r0), "=r"(r1), "=r"(r2), "=r"(r3) : "r"(addr));
}
__device__ __forceinline__ uint32_t smem_u32(const void* p) {
    return (uint32_t)__cvta_generic_to_shared(p);
}
__device__ __forceinline__ void cp_async16(void* smem, const void* gmem) {
    uint32_t s = smem_u32(smem);
    asm volatile("cp.async.cg.shared.global [%0], [%1], 16;\n" :: "r"(s), "l"(gmem));
}
__device__ __forceinline__ void cp_commit() {
    asm volatile("cp.async.commit_group;\n");
}
template<int N> __device__ __forceinline__ void cp_wait() {
    asm volatile("cp.async.wait_group %0;\n" :: "n"(N));
}
__device__ __forceinline__ float bayes_w(float mu, float rho, float eps) {
    float sp = (rho > 15.0f) ? rho : log1pf(__expf(rho));
    return fmaf(sp, eps, mu);
}

// ---------------------------------------------------------------------------
// Prep kernels
// ---------------------------------------------------------------------------
__global__ void round_x_kernel(const float* __restrict__ in,
                               float* __restrict__ out, int n4)
{
    int i = blockIdx.x * 256 + threadIdx.x;
    if (i < n4) ((float4*)out)[i] = f2tf4(((const float4*)in)[i]);
}

__global__ void prep_w_kernel(const float* __restrict__ qw,  const float* __restrict__ kw,
                              const float* __restrict__ vmu, const float* __restrict__ vrho,
                              const float* __restrict__ veps,
                              const float* __restrict__ pmu, const float* __restrict__ prho,
                              const float* __restrict__ peps,
                              const float* __restrict__ pbmu, const float* __restrict__ pbrho,
                              const float* __restrict__ pbeps,
                              float* __restrict__ qwr, float* __restrict__ kwr,
                              float* __restrict__ vw,  float* __restrict__ pw,
                              float* __restrict__ pb)
{
    const int nw = C_DIM * C_DIM;
    int i = blockIdx.x * 256 + threadIdx.x;
    if (i < nw) {
        qwr[i] = f2tf(qw[i] * QSCALE);          // softmax scale folded here
    } else if (i < 2 * nw) {
        int j = i - nw;      kwr[j] = f2tf(kw[j]);
    } else if (i < 3 * nw) {
        int j = i - 2 * nw;  vw[j] = f2tf(bayes_w(vmu[j], vrho[j], veps[j]));
    } else if (i < 4 * nw) {
        int j = i - 3 * nw;  pw[j] = f2tf(bayes_w(pmu[j], prho[j], peps[j]));
    } else if (i < 4 * nw + C_DIM) {
        int j = i - 4 * nw;  pb[j] = bayes_w(pbmu[j], pbrho[j], pbeps[j]);
    }
}

// ---------------------------------------------------------------------------
// TF32 SGEMM (NT): 3-stage cp.async pipeline + ldmatrix fragment loads.
// 128x128x32 tile, 256 threads = 8 warps (2Mx4N), warp tile 64x32.
// m_base: row offset of this chunk (batch chunking). Ndim parameterizes the
// fused QKV (3072) vs projection (1024) output widths.
// ---------------------------------------------------------------------------
#define GBM 128
#define GBN 128
#define GBK 32
#define GSTR 36
#define GTILE (GBM * GSTR)
#define GSTG 3
#define GEMM_SMEM (2 * GSTG * GTILE * 4)   // 110592 B

__global__ __launch_bounds__(256, 2)
void sgemm_tf32(const float* __restrict__ A, const float* __restrict__ B,
                const float* __restrict__ bias, float* __restrict__ Cmat,
                int Kdim, int Ndim, int round_out, int m_base)
{
    extern __shared__ float sm[];
    float* As = sm;                    // [3][GTILE]
    float* Bs = sm + GSTG * GTILE;     // [3][GTILE]

    const int tid  = threadIdx.x;
    const int lane = tid & 31;
    const int w    = tid >> 5;
    const int wm   = w >> 2;
    const int wn   = w & 3;
    const int g    = lane >> 2;
    const int t    = lane & 3;
    const int m0   = m_base + blockIdx.y * GBM;
    const int n0   = blockIdx.x * GBN;

    const uint32_t offA = ((lane & 15) * GSTR) * 4 + (lane >> 4) * 16;
    const uint32_t offB = (((lane & 7) + ((lane & 16) >> 1)) * GSTR) * 4 +
                          ((lane >> 3) & 1) * 16;
    const uint32_t uAs = smem_u32(As);
    const uint32_t uBs = smem_u32(Bs);

    float acc[4][4][4];
#pragma unroll
    for (int i = 0; i < 4; i++)
#pragma unroll
        for (int j = 0; j < 4; j++)
#pragma unroll
            for (int c = 0; c < 4; c++) acc[i][j][c] = 0.0f;

    const int lrow = tid >> 3;              // 0..31
    const int lsg  = (tid & 7) * 4;         // 0,4,...,28
    const int NCH  = Kdim / GBK;            // 32

    #define LOAD_TILES(st, c)                                                   \
        do {                                                                    \
            int k0 = (c) * GBK;                                                 \
            _Pragma("unroll")                                                   \
            for (int it = 0; it < 4; it++) {                                    \
                int row = lrow + it * 32;                                       \
                cp_async16(&As[(st) * GTILE + row * GSTR + lsg],                \
                           A + (size_t)(m0 + row) * Kdim + k0 + lsg);           \
                cp_async16(&Bs[(st) * GTILE + row * GSTR + lsg],                \
                           B + (size_t)(n0 + row) * Kdim + k0 + lsg);           \
            }                                                                   \
            cp_commit();                                                        \
        } while (0)

    LOAD_TILES(0, 0);
    LOAD_TILES(1, 1);

    for (int c = 0; c < NCH; c++) {
        if (c + 2 < NCH) cp_wait<1>();
        else             cp_wait<0>();
        __syncthreads();
        if (c + 2 < NCH) LOAD_TILES((c + 2) % GSTG, c + 2);

        const int s = c % GSTG;
        const uint32_t aBase = uAs + s * GTILE * 4;
        const uint32_t bBase = uBs + s * GTILE * 4;
#pragma unroll
        for (int kk = 0; kk < 4; kk++) {
            const uint32_t kbB = kk * 32;   // kk*8 floats
            uint32_t af[4][4];
#pragma unroll
            for (int mt = 0; mt < 4; mt++)
                ldsm_x4(af[mt][0], af[mt][1], af[mt][2], af[mt][3],
                        aBase + (uint32_t)(wm * 64 + mt * 16) * GSTR * 4 + offA + kbB);
            uint32_t bf[4][2];
#pragma unroll
            for (int p = 0; p < 2; p++)
                ldsm_x4(bf[2 * p][0], bf[2 * p][1], bf[2 * p + 1][0], bf[2 * p + 1][1],
                        bBase + (uint32_t)(wn * 32 + p * 16) * GSTR * 4 + offB + kbB);
#pragma unroll
            for (int mt = 0; mt < 4; mt++)
#pragma unroll
                for (int nt = 0; nt < 4; nt++)
                    mma_tf32(acc[mt][nt], af[mt][0], af[mt][1], af[mt][2], af[mt][3],
                             bf[nt][0], bf[nt][1]);
        }
    }
    #undef LOAD_TILES

    // Epilogue
#pragma unroll
    for (int mt = 0; mt < 4; mt++) {
        int r0 = m0 + wm * 64 + mt * 16 + g;
#pragma unroll
        for (int nt = 0; nt < 4; nt++) {
            int c0 = n0 + wn * 32 + nt * 8 + 2 * t;
            float bx = 0.0f, by = 0.0f;
            if (bias) { bx = bias[c0]; by = bias[c0 + 1]; }
            float2 v0 = make_float2(acc[mt][nt][0] + bx, acc[mt][nt][1] + by);
            float2 v1 = make_float2(acc[mt][nt][2] + bx, acc[mt][nt][3] + by);
            if (round_out) {
                v0.x = f2tf(v0.x); v0.y = f2tf(v0.y);
                v1.x = f2tf(v1.x); v1.y = f2tf(v1.y);
            }
            *(float2*)(Cmat + (size_t)r0 * Ndim + c0)       = v0;
            *(float2*)(Cmat + (size_t)(r0 + 8) * Ndim + c0) = v1;
        }
    }
}

// ---------------------------------------------------------------------------
// TF32 flash attention, BQ=128, reading the fused QKV buffer (row stride
// QKVN; q at col 0, k at col 1024, v at col 2048). Inner loops identical to
// the R16 passing version. O written to a separate [M][C] buffer.
// ---------------------------------------------------------------------------
#define FBQ   128
#define FSTR  68
#define VSTR  72
#define KTILE (64 * FSTR)
#define VTILE (64 * VSTR)
#define PTILE (FBQ * FSTR)
#define FLASH_SMEM ((2 * KTILE + 2 * VTILE + PTILE) * 4)   // 106496 B

__global__ __launch_bounds__(256, 2)
void flash_tf32(const float* __restrict__ QKV, float* __restrict__ O,
                int bh_base)
{
    extern __shared__ float sm[];
    float* Ks = sm;
    float* Vs = sm + 2 * KTILE;
    float* Ps = sm + 2 * KTILE + 2 * VTILE;

    const int tid  = threadIdx.x;
    const int lane = tid & 31;
    const int w    = tid >> 5;
    const int g    = lane >> 2;
    const int t    = lane & 3;
    const int rb   = w * 16;
    const int bh   = bh_base + blockIdx.y;
    const int b    = bh >> 4;
    const int h    = bh & 15;
    const int q0   = blockIdx.x * FBQ;

    const size_t baseQ = ((size_t)b * SEQ + q0) * QKVN + h * D_DIM;
    const size_t baseK = ((size_t)b * SEQ) * QKVN + C_DIM     + h * D_DIM;
    const size_t baseV = ((size_t)b * SEQ) * QKVN + 2 * C_DIM + h * D_DIM;
    const size_t baseO = ((size_t)b * SEQ + q0) * C_DIM + h * D_DIM;

    const int lrow = tid >> 4;
    const int ldq  = (tid & 15) * 4;

    const uint32_t uKs = smem_u32(Ks);
    const uint32_t uPs = smem_u32(Ps);
    const uint32_t offA = ((lane & 15) * FSTR) * 4 + (lane >> 4) * 16;
    const uint32_t offB = (((lane & 7) + ((lane & 16) >> 1)) * FSTR) * 4 +
                          ((lane >> 3) & 1) * 16;

    #define LOAD_KV(st, kt)                                                     \
        do {                                                                    \
            _Pragma("unroll")                                                   \
            for (int it = 0; it < 4; it++) {                                    \
                int row = lrow + it * 16;                                       \
                cp_async16(&Ks[(st) * KTILE + row * FSTR + ldq],                \
                           QKV + baseK + (size_t)((kt) + row) * QKVN + ldq);    \
                cp_async16(&Vs[(st) * VTILE + row * VSTR + ldq],                \
                           QKV + baseV + (size_t)((kt) + row) * QKVN + ldq);    \
            }                                                                   \
            cp_commit();                                                        \
        } while (0)

    LOAD_KV(0, 0);

#pragma unroll
    for (int it = 0; it < 8; it++) {
        int row = lrow + it * 16;
        *(float4*)&Ps[row * FSTR + ldq] =
            *(const float4*)(QKV + baseQ + (size_t)row * QKVN + ldq);
    }
    __syncthreads();

    uint32_t qf[8][4];
#pragma unroll
    for (int kk = 0; kk < 8; kk++)
        ldsm_x4(qf[kk][0], qf[kk][1], qf[kk][2], qf[kk][3],
                uPs + (uint32_t)rb * FSTR * 4 + offA + kk * 32);

    float m0 = -1e30f, m1 = -1e30f, l0 = 0.0f, l1 = 0.0f;
    float oacc[8][4];
#pragma unroll
    for (int nt = 0; nt < 8; nt++)
#pragma unroll
        for (int c = 0; c < 4; c++) oacc[nt][c] = 0.0f;

    int st = 0;
    for (int kt = 0; kt < SEQ; kt += 64) {
        if (kt + 64 < SEQ) { LOAD_KV(st ^ 1, kt + 64); cp_wait<1>(); }
        else               { cp_wait<0>(); }
        __syncthreads();

        const uint32_t kBase = uKs + st * KTILE * 4;
        const float*   Vc    = Vs + st * VTILE;

        float s[8][4];
#pragma unroll
        for (int nt = 0; nt < 8; nt++)
#pragma unroll
            for (int c = 0; c < 4; c++) s[nt][c] = 0.0f;

#pragma unroll
        for (int kk = 0; kk < 8; kk++) {
            const uint32_t kbB = kk * 32;
#pragma unroll
            for (int p = 0; p < 4; p++) {
                uint32_t b0, b1, b2, b3;
                ldsm_x4(b0, b1, b2, b3,
                        kBase + (uint32_t)(p * 16) * FSTR * 4 + offB + kbB);
                mma_tf32(s[2 * p],     qf[kk][0], qf[kk][1], qf[kk][2], qf[kk][3], b0, b1);
                mma_tf32(s[2 * p + 1], qf[kk][0], qf[kk][1], qf[kk][2], qf[kk][3], b2, b3);
            }
        }

        float mx0 = -1e30f, mx1 = -1e30f;
#pragma unroll
        for (int nt = 0; nt < 8; nt++) {
            mx0 = fmaxf(mx0, fmaxf(s[nt][0], s[nt][1]));
            mx1 = fmaxf(mx1, fmaxf(s[nt][2], s[nt][3]));
        }
#pragma unroll
        for (int off = 1; off < 4; off <<= 1) {
            mx0 = fmaxf(mx0, __shfl_xor_sync(0xffffffffu, mx0, off));
            mx1 = fmaxf(mx1, __shfl_xor_sync(0xffffffffu, mx1, off));
        }
        float mn0 = fmaxf(m0, mx0), mn1 = fmaxf(m1, mx1);
        float cr0 = ex2f(m0 - mn0), cr1 = ex2f(m1 - mn1);
        float sum0 = 0.0f, sum1 = 0.0f;
#pragma unroll
        for (int nt = 0; nt < 8; nt++) {
            s[nt][0] = ex2f(s[nt][0] - mn0);
            s[nt][1] = ex2f(s[nt][1] - mn0);
            s[nt][2] = ex2f(s[nt][2] - mn1);
            s[nt][3] = ex2f(s[nt][3] - mn1);
            sum0 += s[nt][0] + s[nt][1];
            sum1 += s[nt][2] + s[nt][3];
        }
#pragma unroll
        for (int off = 1; off < 4; off <<= 1) {
            sum0 += __shfl_xor_sync(0xffffffffu, sum0, off);
            sum1 += __shfl_xor_sync(0xffffffffu, sum1, off);
        }
        l0 = l0 * cr0 + sum0;  m0 = mn0;
        l1 = l1 * cr1 + sum1;  m1 = mn1;
#pragma unroll
        for (int nt = 0; nt < 8; nt++) {
            oacc[nt][0] *= cr0; oacc[nt][1] *= cr0;
            oacc[nt][2] *= cr1; oacc[nt][3] *= cr1;
        }

#pragma unroll
        for (int nt = 0; nt < 8; nt++) {
            *(float2*)&Ps[(rb + g    ) * FSTR + nt * 8 + 2 * t] =
                make_float2(f2tf(s[nt][0]), f2tf(s[nt][1]));
            *(float2*)&Ps[(rb + g + 8) * FSTR + nt * 8 + 2 * t] =
                make_float2(f2tf(s[nt][2]), f2tf(s[nt][3]));
        }
        __syncwarp();

#pragma unroll
        for (int kk = 0; kk < 8; kk++) {
            const int kb = kk * 8;
            uint32_t a0, a1, a2, a3;
            ldsm_x4(a0, a1, a2, a3,
                    uPs + (uint32_t)rb * FSTR * 4 + offA + kk * 32);
#pragma unroll
            for (int nt = 0; nt < 8; nt++) {
                uint32_t b0 = __float_as_uint(Vc[(kb + t    ) * VSTR + nt * 8 + g]);
                uint32_t b1 = __float_as_uint(Vc[(kb + t + 4) * VSTR + nt * 8 + g]);
                mma_tf32(oacc[nt], a0, a1, a2, a3, b0, b1);
            }
        }
        __syncthreads();
        st ^= 1;
    }
    #undef LOAD_KV

    float inv0 = 1.0f / l0, inv1 = 1.0f / l1;
#pragma unroll
    for (int nt = 0; nt < 8; nt++) {
        int c0 = nt * 8 + 2 * t;
        float2 v0 = make_float2(f2tf(oacc[nt][0] * inv0), f2tf(oacc[nt][1] * inv0));
        float2 v1 = make_float2(f2tf(oacc[nt][2] * inv1), f2tf(oacc[nt][3] * inv1));
        *(float2*)(O + baseO + (size_t)(rb + g    ) * C_DIM + c0) = v0;
        *(float2*)(O + baseO + (size_t)(rb + g + 8) * C_DIM + c0) = v1;
    }
}

// ---------------------------------------------------------------------------
// Launch: TWO independent half-batch chains (one created stream).
//   default: round_x ──> chain A: fusedQKV_A, flash_A, proj_A (batches 0-1)
//   s1:      prep_w ───> chain B: fusedQKV_B, flash_B, proj_B (batches 2-3)
// ---------------------------------------------------------------------------
extern "C" void kernel_launch(void* const* d_in, const int* in_sizes, int n_in,
                              void* d_out, int out_size)
{
    const float* x     = (const float*)d_in[0];
    const float* q_w   = (const float*)d_in[1];
    const float* k_w   = (const float*)d_in[2];
    const float* v_mu  = (const float*)d_in[3];
    const float* v_rho = (const float*)d_in[4];
    const float* v_eps = (const float*)d_in[5];
    const float* p_mu  = (const float*)d_in[6];
    const float* p_rho = (const float*)d_in[7];
    const float* p_eps = (const float*)d_in[8];
    const float* pb_mu = (const float*)d_in[9];
    const float* pb_rho= (const float*)d_in[10];
    const float* pb_eps= (const float*)d_in[11];
    float* out = (float*)d_out;

    float *qkvw, *pw, *pb, *xr, *qkv, *o;
    cudaGetSymbolAddress((void**)&qkvw, g_qkvw);
    cudaGetSymbolAddress((void**)&pw,   g_pw);
    cudaGetSymbolAddress((void**)&pb,   g_pb);
    cudaGetSymbolAddress((void**)&xr,   g_xr);
    cudaGetSymbolAddress((void**)&qkv,  g_qkv);
    cudaGetSymbolAddress((void**)&o,    g_o);

    const int nw = C_DIM * C_DIM;
    float* qwr = qkvw;                 // rows 0..1023
    float* kwr = qkvw + (size_t)nw;    // rows 1024..2047
    float* vw  = qkvw + 2 * (size_t)nw;// rows 2048..3071

    static cudaStream_t s1 = nullptr;
    static cudaEvent_t  e0 = nullptr, eX = nullptr, eW = nullptr, eB = nullptr;
    if (!s1) {
        cudaStreamCreateWithFlags(&s1, cudaStreamNonBlocking);
        cudaEventCreateWithFlags(&e0, cudaEventDisableTiming);
        cudaEventCreateWithFlags(&eX, cudaEventDisableTiming);
        cudaEventCreateWithFlags(&eW, cudaEventDisableTiming);
        cudaEventCreateWithFlags(&eB, cudaEventDisableTiming);
        cudaFuncSetAttribute(sgemm_tf32,
                             cudaFuncAttributeMaxDynamicSharedMemorySize, GEMM_SMEM);
        cudaFuncSetAttribute(flash_tf32,
                             cudaFuncAttributeMaxDynamicSharedMemorySize, FLASH_SMEM);
    }

    const int nx4 = M_DIM * C_DIM / 4;
    const int npw = 4 * nw + C_DIM;
    const int HB  = 2 * SEQ;                     // rows per half (2 batches)
    dim3 qgrid(QKVN / GBN, HB / GBM);            // fused QKV: 24x32 = 768 CTAs
    dim3 pgrid(C_DIM / GBN, HB / GBM);           // projection: 8x32 = 256 CTAs
    dim3 fgrid(SEQ / FBQ, 2 * H_DIM);            // flash half: 16x32

    // Fork prep.
    cudaEventRecord(e0, 0);
    cudaStreamWaitEvent(s1, e0, 0);

    round_x_kernel<<<(nx4 + 255) / 256, 256>>>(x, xr, nx4);
    cudaEventRecord(eX, 0);

    prep_w_kernel<<<(npw + 255) / 256, 256, 0, s1>>>(
        q_w, k_w, v_mu, v_rho, v_eps, p_mu, p_rho, p_eps,
        pb_mu, pb_rho, pb_eps, qwr, kwr, vw, pw, pb);
    cudaEventRecord(eW, s1);

    // Chain A (batches 0-1) on default; chain B (batches 2-3) on s1.
    cudaStreamWaitEvent(0, eW, 0);
    cudaStreamWaitEvent(s1, eX, 0);

    sgemm_tf32<<<qgrid, 256, GEMM_SMEM>>>(xr, qkvw, nullptr, qkv,
                                          C_DIM, QKVN, 1, 0);
    flash_tf32<<<fgrid, 256, FLASH_SMEM>>>(qkv, o, 0);
    sgemm_tf32<<<pgrid, 256, GEMM_SMEM>>>(o, pw, pb, out, C_DIM, C_DIM, 0, 0);

    sgemm_tf32<<<qgrid, 256, GEMM_SMEM, s1>>>(xr, qkvw, nullptr, qkv,
                                              C_DIM, QKVN, 1, HB);
    flash_tf32<<<fgrid, 256, FLASH_SMEM, s1>>>(qkv, o, 2 * H_DIM);
    sgemm_tf32<<<pgrid, 256, GEMM_SMEM, s1>>>(o, pw, pb, out, C_DIM, C_DIM, 0, HB);
    cudaEventRecord(eB, s1);

    // Join.
    cudaStreamWaitEvent(0, eB, 0);
}